// round 14
// baseline (speedup 1.0000x reference)
#include <cuda_runtime.h>
#include <cuda_fp16.h>
#include <stdint.h>

#define NQ 10
#define BSZ 32768
#define NT2 512            // 64-row tiles

__device__ __half g_X [2][NT2][2048];     // [dig][tile][64r x 32k, 64B rows sw64]
__device__ __half g_W1[NQ][8192];         // [net][256c x 32k, sw64]
__device__ __half g_W2[NQ][4][2][8192];   // [net][kc][np][128n x 64k, sw128]

__device__ __forceinline__ uint32_t smem_u32(const void* p){
    uint32_t a; asm("{ .reg .u64 t; cvta.to.shared.u64 t, %1; cvt.u32.u64 %0, t; }":"=r"(a):"l"(p)); return a;
}
__device__ __forceinline__ uint32_t sw128(uint32_t o){ return o ^ ((o>>3)&0x70); }
__device__ __forceinline__ uint32_t sw64 (uint32_t o){ return o ^ ((o>>3)&0x30); }
__device__ __forceinline__ void cpa16(uint32_t d, const void* s){
    asm volatile("cp.async.cg.shared.global [%0], [%1], 16;"::"r"(d),"l"(s):"memory");
}
#define CP_COMMIT() asm volatile("cp.async.commit_group;":::"memory")
#define CP_WAIT(n)  asm volatile("cp.async.wait_group %0;"::"n"(n):"memory")
__device__ __forceinline__ void ldm4(uint32_t r[4], uint32_t a){
    asm volatile("ldmatrix.sync.aligned.m8n8.x4.shared.b16 {%0,%1,%2,%3}, [%4];"
        :"=r"(r[0]),"=r"(r[1]),"=r"(r[2]),"=r"(r[3]):"r"(a));
}
__device__ __forceinline__ void hmma(float c[4], const uint32_t a[4], uint32_t b0, uint32_t b1){
    asm volatile("mma.sync.aligned.m16n8k16.row.col.f32.f16.f16.f32 "
        "{%0,%1,%2,%3},{%4,%5,%6,%7},{%8,%9},{%0,%1,%2,%3};"
        :"+f"(c[0]),"+f"(c[1]),"+f"(c[2]),"+f"(c[3])
        :"r"(a[0]),"r"(a[1]),"r"(a[2]),"r"(a[3]),"r"(b0),"r"(b1));
}
__device__ __forceinline__ uint32_t h2(float v0, float v1){
    __half h0=__float2half_rn(v0), h1=__float2half_rn(v1);
    return (uint32_t)__half_as_ushort(h0)|((uint32_t)__half_as_ushort(h1)<<16);
}
__device__ __forceinline__ void split2f(float v0, float v1, uint32_t& hw, uint32_t& lw){
    __half h0=__float2half_rn(v0), h1=__float2half_rn(v1);
    hw=(uint32_t)__half_as_ushort(h0)|((uint32_t)__half_as_ushort(h1)<<16);
    __half g0=__float2half_rn(v0-__half2float(h0)), g1=__float2half_rn(v1-__half2float(h1));
    lw=(uint32_t)__half_as_ushort(g0)|((uint32_t)__half_as_ushort(g1)<<16);
}

// ===================== merged prep (1 launch) =====================
__global__ void __launch_bounds__(128) prep_all(const float* __restrict__ st, const float* __restrict__ ac,
                                                const float* __restrict__ W1, const float* __restrict__ W2){
    const int b=blockIdx.x, tid=threadIdx.x;
    if(b<256){                                  // --- X: 128 rows per block -> two 64-row tiles ---
        int R=b*128+tid, t2=R>>6, rl=R&63;
        uint32_t wh[16], wl[16];
        #pragma unroll
        for(int i=0;i<16;i++){wh[i]=0;wl[i]=0;}
        #pragma unroll
        for(int kp=0;kp<12;kp++){
            int k=kp*2;
            float v0=0.f,v1=0.f;
            if(k<17)v0=st[R*17+k]; else if(k<23)v0=ac[R*6+k-17];
            if(k+1<17)v1=st[R*17+k+1]; else if(k+1<23)v1=ac[R*6+k+1-17];
            split2f(v0,v1,wh[kp],wl[kp]);
        }
        char* dh=(char*)&g_X[0][t2][0]; char* dl=(char*)&g_X[1][t2][0];
        #pragma unroll
        for(int u=0;u<4;u++){
            uint32_t off=sw64((uint32_t)(rl*64+u*16));
            *(uint4*)(dh+off)=make_uint4(wh[4*u],wh[4*u+1],wh[4*u+2],wh[4*u+3]);
            *(uint4*)(dl+off)=make_uint4(wl[4*u],wl[4*u+1],wl[4*u+2],wl[4*u+3]);
        }
    } else if(b<256+NQ){                        // --- W1 ---
        int n=b-256;
        for(int c=tid;c<256;c+=128){
            uint32_t w[16];
            #pragma unroll
            for(int i=0;i<16;i++) w[i]=0;
            #pragma unroll
            for(int kp=0;kp<12;kp++){
                int k=kp*2;
                float v0=(k<23)?W1[(n*23+k)*256+c]:0.f;
                float v1=(k+1<23)?W1[(n*23+k+1)*256+c]:0.f;
                w[kp]=h2(v0,v1);
            }
            char* d=(char*)&g_W1[n][0];
            #pragma unroll
            for(int u=0;u<4;u++){
                uint32_t off=sw64((uint32_t)(c*64+u*16));
                *(uint4*)(d+off)=make_uint4(w[4*u],w[4*u+1],w[4*u+2],w[4*u+3]);
            }
        }
    } else {                                    // --- W2 ---
        int e=b-256-NQ, n=e>>1, np=e&1, nl=tid;
        const float* src=W2+n*65536+np*128+nl;
        for(int kc=0;kc<4;kc++){
            uint32_t w[32];
            #pragma unroll
            for(int kp=0;kp<32;kp++){
                int k=kc*64+kp*2;
                w[kp]=h2(src[k*256],src[(k+1)*256]);
            }
            char* d=(char*)&g_W2[n][kc][np][0];
            #pragma unroll
            for(int u=0;u<8;u++){
                uint32_t off=sw128((uint32_t)(nl*128+u*16));
                *(uint4*)(d+off)=make_uint4(w[4*u],w[4*u+1],w[4*u+2],w[4*u+3]);
            }
        }
    }
}

// ===================== main (256 threads, 2 CTAs/SM) =====================
// A2 [4kc x 8K] @0 (32KB). Phase-1 overlay: Xh@0(4K), Xl@4096(4K), W1@8192(16K).
// W2 ring 3x16K @32768. Misc @81920.
#define SM_A2   0
#define SM_XH   0
#define SM_XL   4096
#define SM_W1   8192
#define SM_RING 32768
#define SM_B1   81920
#define SM_B2   82944
#define SM_W3   83968
#define SM_RED  84992     // [4 wn][64] f32 = 1KB
#define SM_TOT  86016

__global__ void __launch_bounds__(256,2)
qmain(const float* __restrict__ b1,const float* __restrict__ b2,
      const float* __restrict__ W3,const float* __restrict__ b3,float* __restrict__ out){
    extern __shared__ char sm[];
    float* f=(float*)sm;
    const uint32_t sb=smem_u32(sm);
    const int tid=threadIdx.x, wid=tid>>5, lane=tid&31;
    const int tile=blockIdx.x, n=blockIdx.y;
    const int wm=wid&1, wn=wid>>1, R0=wm*32;     // 2 m-warps x 4 n-warps
    const int aRow=(lane&7)+((lane>>3)&1)*8, aCol=(lane>>4)*8;
    const int bRow=(lane&7)+((lane>>4)<<3),  bCol=((lane>>3)&1)*8;
    const int q=lane>>2, s2=(lane&3)*2;

    // G0: X + W1 (24KB). G1,G2: W2 stages 0,1 (16KB each).
    {
        const char* xh=(const char*)&g_X[0][tile][0];
        const char* xl=(const char*)&g_X[1][tile][0];
        for(int i=tid;i<256;i+=256){ cpa16(sb+SM_XH+i*16,xh+i*16); cpa16(sb+SM_XL+i*16,xl+i*16); }
        const char* w1=(const char*)&g_W1[n][0];
        for(int i=tid;i<1024;i+=256) cpa16(sb+SM_W1+i*16,w1+i*16);
        CP_COMMIT();
        const char* s0=(const char*)&g_W2[n][0][0][0];   // stage0: np0,kc0
        for(int i=tid;i<1024;i+=256) cpa16(sb+SM_RING+i*16,s0+i*16);
        CP_COMMIT();
        const char* s1=(const char*)&g_W2[n][1][0][0];   // stage1: np0,kc1
        for(int i=tid;i<1024;i+=256) cpa16(sb+SM_RING+16384+i*16,s1+i*16);
        CP_COMMIT();
    }
    f[SM_B1/4+tid]=b1[n*256+tid];
    f[SM_B2/4+tid]=b2[n*256+tid];
    f[SM_W3/4+tid]=W3[n*256+tid];
    CP_WAIT(2);          // X + W1 ready
    __syncthreads();

    // ---- layer 1: warp 32r x 64c, 2-term (x split, W1 single) ----
    float acc1[2][8][4];
    #pragma unroll
    for(int mt=0;mt<2;mt++)
        #pragma unroll
        for(int nt=0;nt<8;nt++)
            #pragma unroll
            for(int e=0;e<4;e++) acc1[mt][nt][e]=0.f;
    #pragma unroll
    for(int ks=0;ks<2;ks++){
        const int k=ks*16;
        uint32_t ah[2][4],al[2][4];
        #pragma unroll
        for(int mt=0;mt<2;mt++){
            uint32_t o=sw64((uint32_t)((R0+mt*16+aRow)*64+(k+aCol)*2));
            ldm4(ah[mt],sb+SM_XH+o);
            ldm4(al[mt],sb+SM_XL+o);
        }
        #pragma unroll
        for(int p=0;p<4;p++){
            int n0=wn*64+p*16;
            uint32_t ob=sw64((uint32_t)((n0+bRow)*64+(k+bCol)*2));
            uint32_t bw[4];
            ldm4(bw,sb+SM_W1+ob);
            #pragma unroll
            for(int mt=0;mt<2;mt++)
                #pragma unroll
                for(int sub=0;sub<2;sub++){
                    int nt=p*2+sub;
                    hmma(acc1[mt][nt],ah[mt],bw[sub*2],bw[sub*2+1]);
                    hmma(acc1[mt][nt],al[mt],bw[sub*2],bw[sub*2+1]);
                }
        }
    }
    __syncthreads();   // X/W1 reads done; A2 may overwrite

    // ---- epilogue 1: relu(acc1+b1) -> fp16 A2 image (warp's 64 cols = chunk wn) ----
    {
        const float* b1s=f+SM_B1/4;
        #pragma unroll
        for(int mt=0;mt<2;mt++){
            const int r0=R0+mt*16+q;
            #pragma unroll
            for(int nt=0;nt<8;nt++){
                const int c0=wn*64+nt*8+s2;
                const int kk=c0&63;
                const float bb0=b1s[c0], bb1=b1s[c0+1];
                uint32_t hw=h2(fmaxf(acc1[mt][nt][0]+bb0,0.f),fmaxf(acc1[mt][nt][1]+bb1,0.f));
                *(uint32_t*)(sm+SM_A2+wn*8192+sw128((uint32_t)(r0*128+kk*2)))=hw;
                uint32_t hw2=h2(fmaxf(acc1[mt][nt][2]+bb0,0.f),fmaxf(acc1[mt][nt][3]+bb1,0.f));
                *(uint32_t*)(sm+SM_A2+wn*8192+sw128((uint32_t)((r0+8)*128+kk*2)))=hw2;
            }
        }
    }

    // hoisted per-warp ldsm offsets for layer 2
    uint32_t aoff[2], boff[2];
    #pragma unroll
    for(int mt=0;mt<2;mt++)
        aoff[mt]=sw128((uint32_t)((R0+mt*16+aRow)*128+aCol*2));
    #pragma unroll
    for(int p4=0;p4<2;p4++)
        boff[p4]=sw128((uint32_t)((wn*32+p4*16+bRow)*128+bCol*2));

    // ---- layer 2+3: 8 stages (np 0..1 x kc 0..3), 3-deep 16KB ring ----
    float rowsum[4]={0.f,0.f,0.f,0.f};
    float acc[2][4][4];
    #pragma unroll 1
    for(int s=0;s<8;s++){
        const int np=s>>2, kc=s&3, slot=s%3;
        if(s<7) CP_WAIT(1); else CP_WAIT(0);
        __syncthreads();     // stage-s tile ready; (s=0: also A2 visible); prior slot reads ordered
        if(s<6){
            const int t1=s+2;
            const char* src=(const char*)&g_W2[n][t1&3][t1>>2][0];
            uint32_t d=sb+SM_RING+(uint32_t)((t1%3)*16384);
            for(int i=tid;i<1024;i+=256) cpa16(d+i*16,src+i*16);
            CP_COMMIT();
        }
        if(kc==0){
            #pragma unroll
            for(int mt=0;mt<2;mt++)
                #pragma unroll
                for(int nt=0;nt<4;nt++)
                    #pragma unroll
                    for(int e=0;e<4;e++) acc[mt][nt][e]=0.f;
        }
        const uint32_t ab=sb+SM_A2+(uint32_t)(kc*8192);
        const uint32_t bbase=sb+SM_RING+(uint32_t)(slot*16384);
        #pragma unroll
        for(int ks=0;ks<4;ks++){
            const uint32_t kb=(uint32_t)(ks*32);
            uint32_t ah[2][4];
            #pragma unroll
            for(int mt=0;mt<2;mt++)
                ldm4(ah[mt],ab+(aoff[mt]^kb));
            #pragma unroll
            for(int p4=0;p4<2;p4++){
                uint32_t bf[4];
                ldm4(bf,bbase+(boff[p4]^kb));
                #pragma unroll
                for(int mt=0;mt<2;mt++)
                    #pragma unroll
                    for(int sub=0;sub<2;sub++){
                        int nt=p4*2+sub;
                        hmma(acc[mt][nt],ah[mt],bf[sub*2],bf[sub*2+1]);
                    }
            }
        }
        if(kc==3){
            const float2* b2v=(const float2*)(f+SM_B2/4);
            const float2* w3v=(const float2*)(f+SM_W3/4);
            #pragma unroll
            for(int mt=0;mt<2;mt++)
                #pragma unroll
                for(int nt=0;nt<4;nt++){
                    const int c0=np*128+wn*32+nt*8+s2;
                    const float2 bb=b2v[c0>>1];
                    const float2 uu=w3v[c0>>1];
                    rowsum[mt*2+0]+=fmaxf(acc[mt][nt][0]+bb.x,0.f)*uu.x
                                  +fmaxf(acc[mt][nt][1]+bb.y,0.f)*uu.y;
                    rowsum[mt*2+1]+=fmaxf(acc[mt][nt][2]+bb.x,0.f)*uu.x
                                  +fmaxf(acc[mt][nt][3]+bb.y,0.f)*uu.y;
                }
        }
    }

    // ---- reduce + output ----
    #pragma unroll
    for(int i=0;i<4;i++){
        float v=rowsum[i];
        v+=__shfl_xor_sync(0xffffffffu,v,1);
        v+=__shfl_xor_sync(0xffffffffu,v,2);
        if((lane&3)==0) f[SM_RED/4+wn*64+R0+(i>>1)*16+(i&1)*8+q]=v;
    }
    __syncthreads();
    if(tid<64){
        const float* red=f+SM_RED/4;
        out[n*BSZ+tile*64+tid]=red[tid]+red[64+tid]+red[128+tid]+red[192+tid]+b3[n];
    }
}

extern "C" void kernel_launch(void* const* d_in, const int* in_sizes, int n_in,
                              void* d_out, int out_size){
    const float* state =(const float*)d_in[0];
    const float* action=(const float*)d_in[1];
    const float* W1=(const float*)d_in[2];
    const float* b1=(const float*)d_in[3];
    const float* W2=(const float*)d_in[4];
    const float* b2=(const float*)d_in[5];
    const float* W3=(const float*)d_in[6];
    const float* b3=(const float*)d_in[7];
    float* out=(float*)d_out;

    prep_all<<<256+NQ+NQ*2,128>>>(state,action,W1,W2);

    cudaFuncSetAttribute(qmain,cudaFuncAttributeMaxDynamicSharedMemorySize,SM_TOT);
    dim3 grid(NT2,NQ);
    qmain<<<grid,256,SM_TOT>>>(b1,b2,W3,b3,out);
}

// round 15
// speedup vs baseline: 1.0391x; 1.0391x over previous
#include <cuda_runtime.h>
#include <cuda_fp16.h>
#include <stdint.h>

#define NQ 10
#define BSZ 32768
#define NT 256

__device__ __half g_X [2][NT][4096];      // [dig][tile][128r x 32k, 64B rows sw64]
__device__ __half g_W1[NQ][8192];         // [net][256c x 32k, sw64]
__device__ __half g_W2[NQ][2][4][8192];   // [net][np][kc][128n x 64k, sw128]

__device__ __forceinline__ uint32_t smem_u32(const void* p){
    uint32_t a; asm("{ .reg .u64 t; cvta.to.shared.u64 t, %1; cvt.u32.u64 %0, t; }":"=r"(a):"l"(p)); return a;
}
__device__ __forceinline__ uint32_t sw128(uint32_t o){ return o ^ ((o>>3)&0x70); }
__device__ __forceinline__ uint32_t sw64 (uint32_t o){ return o ^ ((o>>3)&0x30); }
__device__ __forceinline__ void cpa16(uint32_t d, const void* s){
    asm volatile("cp.async.cg.shared.global [%0], [%1], 16;"::"r"(d),"l"(s):"memory");
}
#define CP_COMMIT() asm volatile("cp.async.commit_group;":::"memory")
#define CP_WAIT(n)  asm volatile("cp.async.wait_group %0;"::"n"(n):"memory")
__device__ __forceinline__ void ldm4(uint32_t r[4], uint32_t a){
    asm volatile("ldmatrix.sync.aligned.m8n8.x4.shared.b16 {%0,%1,%2,%3}, [%4];"
        :"=r"(r[0]),"=r"(r[1]),"=r"(r[2]),"=r"(r[3]):"r"(a));
}
__device__ __forceinline__ void hmma(float c[4], const uint32_t a[4], uint32_t b0, uint32_t b1){
    asm volatile("mma.sync.aligned.m16n8k16.row.col.f32.f16.f16.f32 "
        "{%0,%1,%2,%3},{%4,%5,%6,%7},{%8,%9},{%0,%1,%2,%3};"
        :"+f"(c[0]),"+f"(c[1]),"+f"(c[2]),"+f"(c[3])
        :"r"(a[0]),"r"(a[1]),"r"(a[2]),"r"(a[3]),"r"(b0),"r"(b1));
}
// fp16-accumulator HMMA: D,C packed half2 x2
__device__ __forceinline__ void hmma16(uint32_t c[2], const uint32_t a[4], uint32_t b0, uint32_t b1){
    asm volatile("mma.sync.aligned.m16n8k16.row.col.f16.f16.f16.f16 "
        "{%0,%1},{%2,%3,%4,%5},{%6,%7},{%0,%1};"
        :"+r"(c[0]),"+r"(c[1])
        :"r"(a[0]),"r"(a[1]),"r"(a[2]),"r"(a[3]),"r"(b0),"r"(b1));
}
__device__ __forceinline__ uint32_t h2(float v0, float v1){
    __half h0=__float2half_rn(v0), h1=__float2half_rn(v1);
    return (uint32_t)__half_as_ushort(h0)|((uint32_t)__half_as_ushort(h1)<<16);
}
__device__ __forceinline__ void split2f(float v0, float v1, uint32_t& hw, uint32_t& lw){
    __half h0=__float2half_rn(v0), h1=__float2half_rn(v1);
    hw=(uint32_t)__half_as_ushort(h0)|((uint32_t)__half_as_ushort(h1)<<16);
    __half g0=__float2half_rn(v0-__half2float(h0)), g1=__float2half_rn(v1-__half2float(h1));
    lw=(uint32_t)__half_as_ushort(g0)|((uint32_t)__half_as_ushort(g1)<<16);
}

// ===================== merged prep (1 launch) =====================
__global__ void __launch_bounds__(128) prep_all(const float* __restrict__ st, const float* __restrict__ ac,
                                                const float* __restrict__ W1, const float* __restrict__ W2){
    const int b=blockIdx.x, tid=threadIdx.x;
    if(b<NT){                                   // --- X tiles ---
        int t=b, r=tid, R=t*128+r;
        uint32_t wh[16], wl[16];
        #pragma unroll
        for(int i=0;i<16;i++){wh[i]=0;wl[i]=0;}
        #pragma unroll
        for(int kp=0;kp<12;kp++){
            int k=kp*2;
            float v0=0.f,v1=0.f;
            if(k<17)v0=st[R*17+k]; else if(k<23)v0=ac[R*6+k-17];
            if(k+1<17)v1=st[R*17+k+1]; else if(k+1<23)v1=ac[R*6+k+1-17];
            split2f(v0,v1,wh[kp],wl[kp]);
        }
        char* dh=(char*)&g_X[0][t][0]; char* dl=(char*)&g_X[1][t][0];
        #pragma unroll
        for(int u=0;u<4;u++){
            uint32_t off=sw64((uint32_t)(r*64+u*16));
            *(uint4*)(dh+off)=make_uint4(wh[4*u],wh[4*u+1],wh[4*u+2],wh[4*u+3]);
            *(uint4*)(dl+off)=make_uint4(wl[4*u],wl[4*u+1],wl[4*u+2],wl[4*u+3]);
        }
    } else if(b<NT+NQ){                         // --- W1 ---
        int n=b-NT;
        for(int c=tid;c<256;c+=128){
            uint32_t w[16];
            #pragma unroll
            for(int i=0;i<16;i++) w[i]=0;
            #pragma unroll
            for(int kp=0;kp<12;kp++){
                int k=kp*2;
                float v0=(k<23)?W1[(n*23+k)*256+c]:0.f;
                float v1=(k+1<23)?W1[(n*23+k+1)*256+c]:0.f;
                w[kp]=h2(v0,v1);
            }
            char* d=(char*)&g_W1[n][0];
            #pragma unroll
            for(int u=0;u<4;u++){
                uint32_t off=sw64((uint32_t)(c*64+u*16));
                *(uint4*)(d+off)=make_uint4(w[4*u],w[4*u+1],w[4*u+2],w[4*u+3]);
            }
        }
    } else {                                    // --- W2 ---
        int e=b-NT-NQ, n=e>>1, np=e&1, nl=tid;
        const float* src=W2+n*65536+np*128+nl;
        for(int kc=0;kc<4;kc++){
            uint32_t w[32];
            #pragma unroll
            for(int kp=0;kp<32;kp++){
                int k=kc*64+kp*2;
                w[kp]=h2(src[k*256],src[(k+1)*256]);
            }
            char* d=(char*)&g_W2[n][np][kc][0];
            #pragma unroll
            for(int u=0;u<8;u++){
                uint32_t off=sw128((uint32_t)(nl*128+u*16));
                *(uint4*)(d+off)=make_uint4(w[4*u],w[4*u+1],w[4*u+2],w[4*u+3]);
            }
        }
    }
}

// ===================== main (512 threads, 16 warps, 1 CTA/SM) =====================
// A2 [4kc x 16K] @0 (64KB). Phase-1 overlay: Xh@0(8K), Xl@8192(8K), W1@16384(16K).
// W2 resident @65536 (128KB). Misc @196608.
#define SM_A2  0
#define SM_XH  0
#define SM_XL  8192
#define SM_W1  16384
#define SM_W2  65536
#define SM_B1  196608
#define SM_B2  197632
#define SM_W3  198656
#define SM_RED 199680      // [4 wn][128] f32 = 2KB
#define SM_TOT 201728

__global__ void __launch_bounds__(512,1)
qmain(const float* __restrict__ b1,const float* __restrict__ b2,
      const float* __restrict__ W3,const float* __restrict__ b3,float* __restrict__ out){
    extern __shared__ char sm[];
    float* f=(float*)sm;
    const uint32_t sb=smem_u32(sm);
    const int tid=threadIdx.x, wid=tid>>5, lane=tid&31;
    const int tile=blockIdx.x, n=blockIdx.y;
    const int wm=wid&3, wn=wid>>2, R0=wm*32;     // 4 m-warps x 4 n-warps
    const int aRow=(lane&7)+((lane>>3)&1)*8, aCol=(lane>>4)*8;
    const int bRow=(lane&7)+((lane>>4)<<3),  bCol=((lane>>3)&1)*8;
    const int q=lane>>2, s2=(lane&3)*2;

    // G0: X + W1 (32KB); G1: W2 (128KB)
    {
        const char* xh=(const char*)&g_X[0][tile][0];
        const char* xl=(const char*)&g_X[1][tile][0];
        for(int i=tid;i<512;i+=512){ cpa16(sb+SM_XH+i*16,xh+i*16); cpa16(sb+SM_XL+i*16,xl+i*16); }
        const char* w1=(const char*)&g_W1[n][0];
        for(int i=tid;i<1024;i+=512) cpa16(sb+SM_W1+i*16,w1+i*16);
        CP_COMMIT();
        const char* w2=(const char*)&g_W2[n][0][0][0];
        for(int i=tid;i<8192;i+=512) cpa16(sb+SM_W2+i*16,w2+i*16);
        CP_COMMIT();
    }
    if(tid<256){
        f[SM_B1/4+tid]=b1[n*256+tid];
        f[SM_B2/4+tid]=b2[n*256+tid];
        f[SM_W3/4+tid]=W3[n*256+tid];
    }
    CP_WAIT(1);          // X + W1 ready
    __syncthreads();

    // ---- layer 1: warp 32r x 64c, 2-term (x split, W1 single), f32 acc ----
    float acc1[2][8][4];
    #pragma unroll
    for(int mt=0;mt<2;mt++)
        #pragma unroll
        for(int nt=0;nt<8;nt++)
            #pragma unroll
            for(int e=0;e<4;e++) acc1[mt][nt][e]=0.f;
    #pragma unroll
    for(int ks=0;ks<2;ks++){
        const int k=ks*16;
        uint32_t ah[2][4],al[2][4];
        #pragma unroll
        for(int mt=0;mt<2;mt++){
            uint32_t o=sw64((uint32_t)((R0+mt*16+aRow)*64+(k+aCol)*2));
            ldm4(ah[mt],sb+SM_XH+o);
            ldm4(al[mt],sb+SM_XL+o);
        }
        #pragma unroll
        for(int p=0;p<4;p++){
            int n0=wn*64+p*16;
            uint32_t ob=sw64((uint32_t)((n0+bRow)*64+(k+bCol)*2));
            uint32_t bw[4];
            ldm4(bw,sb+SM_W1+ob);
            #pragma unroll
            for(int mt=0;mt<2;mt++)
                #pragma unroll
                for(int sub=0;sub<2;sub++){
                    int nt=p*2+sub;
                    hmma(acc1[mt][nt],ah[mt],bw[sub*2],bw[sub*2+1]);
                    hmma(acc1[mt][nt],al[mt],bw[sub*2],bw[sub*2+1]);
                }
        }
    }
    __syncthreads();   // X/W1 reads done; A2 may overwrite

    // ---- epilogue 1: relu(acc1+b1) -> fp16 A2 image (warp's 64 cols = chunk wn) ----
    {
        const float* b1s=f+SM_B1/4;
        #pragma unroll
        for(int mt=0;mt<2;mt++){
            const int r0=R0+mt*16+q;
            #pragma unroll
            for(int nt=0;nt<8;nt++){
                const int c0=wn*64+nt*8+s2;
                const int kk=c0&63;
                const float bb0=b1s[c0], bb1=b1s[c0+1];
                uint32_t hw=h2(fmaxf(acc1[mt][nt][0]+bb0,0.f),fmaxf(acc1[mt][nt][1]+bb1,0.f));
                *(uint32_t*)(sm+SM_A2+wn*16384+sw128((uint32_t)(r0*128+kk*2)))=hw;
                uint32_t hw2=h2(fmaxf(acc1[mt][nt][2]+bb0,0.f),fmaxf(acc1[mt][nt][3]+bb1,0.f));
                *(uint32_t*)(sm+SM_A2+wn*16384+sw128((uint32_t)((r0+8)*128+kk*2)))=hw2;
            }
        }
    }
    CP_WAIT(0);          // W2 fully resident
    __syncthreads();     // A2 visible

    // ---- layer 2: f16 accumulators, two K-banks (kc0-1 -> cfA, kc2-3 -> cfB) ----
    uint32_t cfA[2][8][2], cfB[2][8][2];
    #pragma unroll
    for(int mt=0;mt<2;mt++)
        #pragma unroll
        for(int nt=0;nt<8;nt++){
            cfA[mt][nt][0]=0u; cfA[mt][nt][1]=0u;
            cfB[mt][nt][0]=0u; cfB[mt][nt][1]=0u;
        }

    const int np=wn>>1, nbase=(wn&1)*64;   // global cols [wn*64, wn*64+64)
    #pragma unroll
    for(int kc=0;kc<4;kc++){
        const uint32_t ab=sb+SM_A2+(uint32_t)(kc*16384);
        const uint32_t bbase=sb+SM_W2+(uint32_t)((np*4+kc)*16384);
        #pragma unroll
        for(int ks=0;ks<4;ks++){
            const int k=ks*16;
            uint32_t ah[2][4];
            #pragma unroll
            for(int mt=0;mt<2;mt++){
                uint32_t o=sw128((uint32_t)((R0+mt*16+aRow)*128+(k+aCol)*2));
                ldm4(ah[mt],ab+o);
            }
            #pragma unroll
            for(int p4=0;p4<4;p4++){
                int nl=nbase+p4*16;
                uint32_t ob=sw128((uint32_t)((nl+bRow)*128+(k+bCol)*2));
                uint32_t bf[4];
                ldm4(bf,bbase+ob);
                #pragma unroll
                for(int mt=0;mt<2;mt++)
                    #pragma unroll
                    for(int sub=0;sub<2;sub++){
                        int nt=p4*2+sub;
                        if(kc<2){
                            hmma16(cfA[mt][nt],ah[mt],bf[sub*2],bf[sub*2+1]);
                        }else{
                            hmma16(cfB[mt][nt],ah[mt],bf[sub*2],bf[sub*2+1]);
                        }
                    }
            }
        }
    }

    // ---- layer 3 fold (f16 banks -> f32) + reduce ----
    float rowsum[4]={0.f,0.f,0.f,0.f};
    {
        const float2* b2v=(const float2*)(f+SM_B2/4);
        const float2* w3v=(const float2*)(f+SM_W3/4);
        #pragma unroll
        for(int mt=0;mt<2;mt++)
            #pragma unroll
            for(int nt=0;nt<8;nt++){
                const int c0=wn*64+nt*8+s2;
                const float2 bb=b2v[c0>>1];
                const float2 uu=w3v[c0>>1];
                float2 a01=__half22float2(*reinterpret_cast<__half2*>(&cfA[mt][nt][0]));
                float2 b01=__half22float2(*reinterpret_cast<__half2*>(&cfB[mt][nt][0]));
                float2 a23=__half22float2(*reinterpret_cast<__half2*>(&cfA[mt][nt][1]));
                float2 b23=__half22float2(*reinterpret_cast<__half2*>(&cfB[mt][nt][1]));
                float e0=a01.x+b01.x, e1=a01.y+b01.y;
                float e2=a23.x+b23.x, e3=a23.y+b23.y;
                rowsum[mt*2+0]+=fmaxf(e0+bb.x,0.f)*uu.x+fmaxf(e1+bb.y,0.f)*uu.y;
                rowsum[mt*2+1]+=fmaxf(e2+bb.x,0.f)*uu.x+fmaxf(e3+bb.y,0.f)*uu.y;
            }
    }
    #pragma unroll
    for(int i=0;i<4;i++){
        float v=rowsum[i];
        v+=__shfl_xor_sync(0xffffffffu,v,1);
        v+=__shfl_xor_sync(0xffffffffu,v,2);
        if((lane&3)==0) f[SM_RED/4+wn*128+R0+(i>>1)*16+(i&1)*8+q]=v;
    }
    __syncthreads();
    if(tid<128){
        const float* red=f+SM_RED/4;
        out[n*BSZ+tile*128+tid]=red[tid]+red[128+tid]+red[256+tid]+red[384+tid]+b3[n];
    }
}

extern "C" void kernel_launch(void* const* d_in, const int* in_sizes, int n_in,
                              void* d_out, int out_size){
    const float* state =(const float*)d_in[0];
    const float* action=(const float*)d_in[1];
    const float* W1=(const float*)d_in[2];
    const float* b1=(const float*)d_in[3];
    const float* W2=(const float*)d_in[4];
    const float* b2=(const float*)d_in[5];
    const float* W3=(const float*)d_in[6];
    const float* b3=(const float*)d_in[7];
    float* out=(float*)d_out;

    prep_all<<<NT+NQ+NQ*2,128>>>(state,action,W1,W2);

    cudaFuncSetAttribute(qmain,cudaFuncAttributeMaxDynamicSharedMemorySize,SM_TOT);
    dim3 grid(NT,NQ);
    qmain<<<grid,512,SM_TOT>>>(b1,b2,W3,b3,out);
}

// round 16
// speedup vs baseline: 1.0766x; 1.0361x over previous
#include <cuda_runtime.h>
#include <cuda_fp16.h>
#include <stdint.h>

#define NQ 10
#define BSZ 32768
#define NT 256
#define GRID 296

__device__ __half g_X [2][NT][4096];      // [dig][tile][128r x 32k, 64B rows sw64]
__device__ __half g_W1[NQ][8192];         // [net][256c x 32k, sw64]
__device__ __half g_W2[NQ][2][4][8192];   // [net][np][kc][128n x 64k, sw128]

__device__ __forceinline__ uint32_t smem_u32(const void* p){
    uint32_t a; asm("{ .reg .u64 t; cvta.to.shared.u64 t, %1; cvt.u32.u64 %0, t; }":"=r"(a):"l"(p)); return a;
}
__device__ __forceinline__ uint32_t sw128(uint32_t o){ return o ^ ((o>>3)&0x70); }
__device__ __forceinline__ uint32_t sw64 (uint32_t o){ return o ^ ((o>>3)&0x30); }
__device__ __forceinline__ void cpa16(uint32_t d, const void* s){
    asm volatile("cp.async.cg.shared.global [%0], [%1], 16;"::"r"(d),"l"(s):"memory");
}
#define CP_COMMIT() asm volatile("cp.async.commit_group;":::"memory")
#define CP_WAIT(n)  asm volatile("cp.async.wait_group %0;"::"n"(n):"memory")
__device__ __forceinline__ void ldm4(uint32_t r[4], uint32_t a){
    asm volatile("ldmatrix.sync.aligned.m8n8.x4.shared.b16 {%0,%1,%2,%3}, [%4];"
        :"=r"(r[0]),"=r"(r[1]),"=r"(r[2]),"=r"(r[3]):"r"(a));
}
__device__ __forceinline__ void hmma(float c[4], const uint32_t a[4], uint32_t b0, uint32_t b1){
    asm volatile("mma.sync.aligned.m16n8k16.row.col.f32.f16.f16.f32 "
        "{%0,%1,%2,%3},{%4,%5,%6,%7},{%8,%9},{%0,%1,%2,%3};"
        :"+f"(c[0]),"+f"(c[1]),"+f"(c[2]),"+f"(c[3])
        :"r"(a[0]),"r"(a[1]),"r"(a[2]),"r"(a[3]),"r"(b0),"r"(b1));
}
__device__ __forceinline__ uint32_t h2(float v0, float v1){
    __half h0=__float2half_rn(v0), h1=__float2half_rn(v1);
    return (uint32_t)__half_as_ushort(h0)|((uint32_t)__half_as_ushort(h1)<<16);
}
__device__ __forceinline__ void split2f(float v0, float v1, uint32_t& hw, uint32_t& lw){
    __half h0=__float2half_rn(v0), h1=__float2half_rn(v1);
    hw=(uint32_t)__half_as_ushort(h0)|((uint32_t)__half_as_ushort(h1)<<16);
    __half g0=__float2half_rn(v0-__half2float(h0)), g1=__float2half_rn(v1-__half2float(h1));
    lw=(uint32_t)__half_as_ushort(g0)|((uint32_t)__half_as_ushort(g1)<<16);
}

// ===================== merged prep (1 launch) =====================
__global__ void __launch_bounds__(128) prep_all(const float* __restrict__ st, const float* __restrict__ ac,
                                                const float* __restrict__ W1, const float* __restrict__ W2){
    const int b=blockIdx.x, tid=threadIdx.x;
    if(b<NT){                                   // --- X tiles ---
        int t=b, r=tid, R=t*128+r;
        uint32_t wh[16], wl[16];
        #pragma unroll
        for(int i=0;i<16;i++){wh[i]=0;wl[i]=0;}
        #pragma unroll
        for(int kp=0;kp<12;kp++){
            int k=kp*2;
            float v0=0.f,v1=0.f;
            if(k<17)v0=st[R*17+k]; else if(k<23)v0=ac[R*6+k-17];
            if(k+1<17)v1=st[R*17+k+1]; else if(k+1<23)v1=ac[R*6+k+1-17];
            split2f(v0,v1,wh[kp],wl[kp]);
        }
        char* dh=(char*)&g_X[0][t][0]; char* dl=(char*)&g_X[1][t][0];
        #pragma unroll
        for(int u=0;u<4;u++){
            uint32_t off=sw64((uint32_t)(r*64+u*16));
            *(uint4*)(dh+off)=make_uint4(wh[4*u],wh[4*u+1],wh[4*u+2],wh[4*u+3]);
            *(uint4*)(dl+off)=make_uint4(wl[4*u],wl[4*u+1],wl[4*u+2],wl[4*u+3]);
        }
    } else if(b<NT+NQ){                         // --- W1 ---
        int n=b-NT;
        for(int c=tid;c<256;c+=128){
            uint32_t w[16];
            #pragma unroll
            for(int i=0;i<16;i++) w[i]=0;
            #pragma unroll
            for(int kp=0;kp<12;kp++){
                int k=kp*2;
                float v0=(k<23)?W1[(n*23+k)*256+c]:0.f;
                float v1=(k+1<23)?W1[(n*23+k+1)*256+c]:0.f;
                w[kp]=h2(v0,v1);
            }
            char* d=(char*)&g_W1[n][0];
            #pragma unroll
            for(int u=0;u<4;u++){
                uint32_t off=sw64((uint32_t)(c*64+u*16));
                *(uint4*)(d+off)=make_uint4(w[4*u],w[4*u+1],w[4*u+2],w[4*u+3]);
            }
        }
    } else {                                    // --- W2 ---
        int e=b-NT-NQ, n=e>>1, np=e&1, nl=tid;
        const float* src=W2+n*65536+np*128+nl;
        for(int kc=0;kc<4;kc++){
            uint32_t w[32];
            #pragma unroll
            for(int kp=0;kp<32;kp++){
                int k=kc*64+kp*2;
                w[kp]=h2(src[k*256],src[(k+1)*256]);
            }
            char* d=(char*)&g_W2[n][np][kc][0];
            #pragma unroll
            for(int u=0;u<8;u++){
                uint32_t off=sw128((uint32_t)(nl*128+u*16));
                *(uint4*)(d+off)=make_uint4(w[4*u],w[4*u+1],w[4*u+2],w[4*u+3]);
            }
        }
    }
}

// ===================== main (persistent, 512 threads, 1 CTA/SM) =====================
// NO overlays: A2 @0 (64K), W2 @65536 (128K), W1 @196608 (16K),
// XH @212992 (8K), XL @221184 (8K), RED @229376 (2K). Total 231424.
#define SM_A2  0
#define SM_W2  65536
#define SM_W1  196608
#define SM_XH  212992
#define SM_XL  221184
#define SM_RED 229376
#define SM_TOT 231424

__global__ void __launch_bounds__(512,1)
qmain(const float* __restrict__ b1,const float* __restrict__ b2,
      const float* __restrict__ W3,const float* __restrict__ b3,float* __restrict__ out){
    extern __shared__ char sm[];
    float* f=(float*)sm;
    const uint32_t sb=smem_u32(sm);
    const int tid=threadIdx.x, wid=tid>>5, lane=tid&31;
    const int wm=wid&3, wn=wid>>2, R0=wm*32;     // 4 m-warps x 4 n-warps
    const int aRow=(lane&7)+((lane>>3)&1)*8, aCol=(lane>>4)*8;
    const int bRow=(lane&7)+((lane>>4)<<3),  bCol=((lane>>3)&1)*8;
    const int q=lane>>2, s2=(lane&3)*2;
    const int np=wn>>1, nbase=(wn&1)*64;

    // static unit range: units 0..2559 flattened n-major (unit = n*256 + tile)
    const int c=blockIdx.x;
    int u    = (c<192)? c*9 : 1728+(c-192)*8;
    const int uend = u + ((c<192)?9:8);
    int n = u>>8;

    // cold load: G0 = X(u)+W1(n), G1 = W2(n)
    {
        const char* xh=(const char*)&g_X[0][u&255][0];
        const char* xl=(const char*)&g_X[1][u&255][0];
        cpa16(sb+SM_XH+tid*16,xh+tid*16); cpa16(sb+SM_XL+tid*16,xl+tid*16);
        const char* w1=(const char*)&g_W1[n][0];
        for(int i=tid;i<1024;i+=512) cpa16(sb+SM_W1+i*16,w1+i*16);
        CP_COMMIT();
        const char* w2=(const char*)&g_W2[n][0][0][0];
        for(int i=tid;i<8192;i+=512) cpa16(sb+SM_W2+i*16,w2+i*16);
        CP_COMMIT();
    }
    CP_WAIT(1);      // X + W1 ready (W2 in flight)
    __syncthreads();
    bool w2_pending=true;

    while(true){
        const int tile=u&255;

        // ---- layer 1: warp 32r x 64c, 2-term (x split, W1 single) ----
        float acc1[2][8][4];
        #pragma unroll
        for(int mt=0;mt<2;mt++)
            #pragma unroll
            for(int nt=0;nt<8;nt++)
                #pragma unroll
                for(int e=0;e<4;e++) acc1[mt][nt][e]=0.f;
        #pragma unroll
        for(int ks=0;ks<2;ks++){
            const int k=ks*16;
            uint32_t ah[2][4],al[2][4];
            #pragma unroll
            for(int mt=0;mt<2;mt++){
                uint32_t o=sw64((uint32_t)((R0+mt*16+aRow)*64+(k+aCol)*2));
                ldm4(ah[mt],sb+SM_XH+o);
                ldm4(al[mt],sb+SM_XL+o);
            }
            #pragma unroll
            for(int p=0;p<4;p++){
                int n0=wn*64+p*16;
                uint32_t ob=sw64((uint32_t)((n0+bRow)*64+(k+bCol)*2));
                uint32_t bw[4];
                ldm4(bw,sb+SM_W1+ob);
                #pragma unroll
                for(int mt=0;mt<2;mt++)
                    #pragma unroll
                    for(int sub=0;sub<2;sub++){
                        int nt=p*2+sub;
                        hmma(acc1[mt][nt],ah[mt],bw[sub*2],bw[sub*2+1]);
                        hmma(acc1[mt][nt],al[mt],bw[sub*2],bw[sub*2+1]);
                    }
            }
        }
        __syncthreads();   // all warps done reading X buffer

        const int un=u+1;
        const bool havenext=(un<uend);
        const bool samen=havenext && ((un>>8)==n);
        if(samen){         // prefetch X(u+1) into X buffer (free after layer1)
            const char* xh=(const char*)&g_X[0][un&255][0];
            const char* xl=(const char*)&g_X[1][un&255][0];
            cpa16(sb+SM_XH+tid*16,xh+tid*16); cpa16(sb+SM_XL+tid*16,xl+tid*16);
            CP_COMMIT();
        }

        // ---- epilogue 1: relu(acc1+b1) -> fp16 A2 image (warp's 64 cols = chunk wn) ----
        {
            const float2* b1v=(const float2*)(b1+n*256);
            #pragma unroll
            for(int mt=0;mt<2;mt++){
                const int r0=R0+mt*16+q;
                #pragma unroll
                for(int nt=0;nt<8;nt++){
                    const int c0=wn*64+nt*8+s2;
                    const int kk=c0&63;
                    const float2 bb=__ldg(&b1v[c0>>1]);
                    uint32_t hw=h2(fmaxf(acc1[mt][nt][0]+bb.x,0.f),fmaxf(acc1[mt][nt][1]+bb.y,0.f));
                    *(uint32_t*)(sm+SM_A2+wn*16384+sw128((uint32_t)(r0*128+kk*2)))=hw;
                    uint32_t hw2=h2(fmaxf(acc1[mt][nt][2]+bb.x,0.f),fmaxf(acc1[mt][nt][3]+bb.y,0.f));
                    *(uint32_t*)(sm+SM_A2+wn*16384+sw128((uint32_t)((r0+8)*128+kk*2)))=hw2;
                }
            }
        }
        if(w2_pending){ if(samen) CP_WAIT(1); else CP_WAIT(0); w2_pending=false; }
        __syncthreads();   // A2 visible + W2 resident

        // ---- layer 2: warp 32r x 64 global cols, single term ----
        float acc[2][8][4];
        #pragma unroll
        for(int mt=0;mt<2;mt++)
            #pragma unroll
            for(int nt=0;nt<8;nt++)
                #pragma unroll
                for(int e=0;e<4;e++) acc[mt][nt][e]=0.f;
        #pragma unroll 1
        for(int kc=0;kc<4;kc++){
            const uint32_t ab=sb+SM_A2+(uint32_t)(kc*16384);
            const uint32_t bbase=sb+SM_W2+(uint32_t)((np*4+kc)*16384);
            #pragma unroll
            for(int ks=0;ks<4;ks++){
                const int k=ks*16;
                uint32_t ah[2][4];
                #pragma unroll
                for(int mt=0;mt<2;mt++){
                    uint32_t o=sw128((uint32_t)((R0+mt*16+aRow)*128+(k+aCol)*2));
                    ldm4(ah[mt],ab+o);
                }
                #pragma unroll
                for(int p4=0;p4<4;p4++){
                    int nl=nbase+p4*16;
                    uint32_t ob=sw128((uint32_t)((nl+bRow)*128+(k+bCol)*2));
                    uint32_t bf[4];
                    ldm4(bf,bbase+ob);
                    #pragma unroll
                    for(int mt=0;mt<2;mt++)
                        #pragma unroll
                        for(int sub=0;sub<2;sub++){
                            int nt=p4*2+sub;
                            hmma(acc[mt][nt],ah[mt],bf[sub*2],bf[sub*2+1]);
                        }
                }
            }
        }

        // ---- layer 3 fold + reduce ----
        float rowsum[4]={0.f,0.f,0.f,0.f};
        {
            const float2* b2v=(const float2*)(b2+n*256);
            const float2* w3v=(const float2*)(W3+n*256);
            #pragma unroll
            for(int mt=0;mt<2;mt++)
                #pragma unroll
                for(int nt=0;nt<8;nt++){
                    const int c0=wn*64+nt*8+s2;
                    const float2 bb=__ldg(&b2v[c0>>1]);
                    const float2 uu=__ldg(&w3v[c0>>1]);
                    rowsum[mt*2+0]+=fmaxf(acc[mt][nt][0]+bb.x,0.f)*uu.x
                                  +fmaxf(acc[mt][nt][1]+bb.y,0.f)*uu.y;
                    rowsum[mt*2+1]+=fmaxf(acc[mt][nt][2]+bb.x,0.f)*uu.x
                                  +fmaxf(acc[mt][nt][3]+bb.y,0.f)*uu.y;
                }
        }
        #pragma unroll
        for(int i=0;i<4;i++){
            float v=rowsum[i];
            v+=__shfl_xor_sync(0xffffffffu,v,1);
            v+=__shfl_xor_sync(0xffffffffu,v,2);
            if((lane&3)==0) f[SM_RED/4+wn*128+R0+(i>>1)*16+(i&1)*8+q]=v;
        }
        if(samen) CP_WAIT(0);   // X(u+1) landed
        __syncthreads();
        if(tid<128){
            const float* red=f+SM_RED/4;
            out[n*BSZ+tile*128+tid]=red[tid]+red[128+tid]+red[256+tid]+red[384+tid]+__ldg(b3+n);
        }

        if(!havenext) break;
        u=un;
        if(!samen){
            // net (and/or range) boundary: cold reload X(u), W1(n'), W2(n')
            n=u>>8;
            __syncthreads();   // all layer-2 W2 reads + RED reads done
            const char* xh=(const char*)&g_X[0][u&255][0];
            const char* xl=(const char*)&g_X[1][u&255][0];
            cpa16(sb+SM_XH+tid*16,xh+tid*16); cpa16(sb+SM_XL+tid*16,xl+tid*16);
            const char* w1=(const char*)&g_W1[n][0];
            for(int i=tid;i<1024;i+=512) cpa16(sb+SM_W1+i*16,w1+i*16);
            CP_COMMIT();
            const char* w2=(const char*)&g_W2[n][0][0][0];
            for(int i=tid;i<8192;i+=512) cpa16(sb+SM_W2+i*16,w2+i*16);
            CP_COMMIT();
            CP_WAIT(1);
            __syncthreads();
            w2_pending=true;
        }
    }
}

extern "C" void kernel_launch(void* const* d_in, const int* in_sizes, int n_in,
                              void* d_out, int out_size){
    const float* state =(const float*)d_in[0];
    const float* action=(const float*)d_in[1];
    const float* W1=(const float*)d_in[2];
    const float* b1=(const float*)d_in[3];
    const float* W2=(const float*)d_in[4];
    const float* b2=(const float*)d_in[5];
    const float* W3=(const float*)d_in[6];
    const float* b3=(const float*)d_in[7];
    float* out=(float*)d_out;

    prep_all<<<NT+NQ+NQ*2,128>>>(state,action,W1,W2);

    cudaFuncSetAttribute(qmain,cudaFuncAttributeMaxDynamicSharedMemorySize,SM_TOT);
    qmain<<<GRID,512,SM_TOT>>>(b1,b2,W3,b3,out);
}

// round 17
// speedup vs baseline: 1.1613x; 1.0787x over previous
#include <cuda_runtime.h>
#include <cuda_fp16.h>
#include <stdint.h>

#define NQ 10
#define BSZ 32768
#define NT2 512
#define GRID 296

__device__ __half g_X [2][NT2][2048];     // [dig][tile64][64r x 32k, sw64]
__device__ __half g_W1[NQ][8192];         // [net][256c x 32k, sw64]
__device__ __half g_W2[NQ][2][4][8192];   // [net][np][kc][128n x 64k, sw128]

__device__ __forceinline__ uint32_t smem_u32(const void* p){
    uint32_t a; asm("{ .reg .u64 t; cvta.to.shared.u64 t, %1; cvt.u32.u64 %0, t; }":"=r"(a):"l"(p)); return a;
}
__device__ __forceinline__ uint32_t sw128(uint32_t o){ return o ^ ((o>>3)&0x70); }
__device__ __forceinline__ uint32_t sw64 (uint32_t o){ return o ^ ((o>>3)&0x30); }
__device__ __forceinline__ void cpa16(uint32_t d, const void* s){
    asm volatile("cp.async.cg.shared.global [%0], [%1], 16;"::"r"(d),"l"(s):"memory");
}
#define CP_COMMIT() asm volatile("cp.async.commit_group;":::"memory")
#define CP_WAIT(n)  asm volatile("cp.async.wait_group %0;"::"n"(n):"memory")
__device__ __forceinline__ void ldm4(uint32_t r[4], uint32_t a){
    asm volatile("ldmatrix.sync.aligned.m8n8.x4.shared.b16 {%0,%1,%2,%3}, [%4];"
        :"=r"(r[0]),"=r"(r[1]),"=r"(r[2]),"=r"(r[3]):"r"(a));
}
__device__ __forceinline__ void hmma(float c[4], const uint32_t a[4], uint32_t b0, uint32_t b1){
    asm volatile("mma.sync.aligned.m16n8k16.row.col.f32.f16.f16.f32 "
        "{%0,%1,%2,%3},{%4,%5,%6,%7},{%8,%9},{%0,%1,%2,%3};"
        :"+f"(c[0]),"+f"(c[1]),"+f"(c[2]),"+f"(c[3])
        :"r"(a[0]),"r"(a[1]),"r"(a[2]),"r"(a[3]),"r"(b0),"r"(b1));
}
__device__ __forceinline__ uint32_t h2(float v0, float v1){
    uint32_t r; asm("cvt.rn.f16x2.f32 %0, %1, %2;":"=r"(r):"f"(v1),"f"(v0)); return r;
}
__device__ __forceinline__ void split2f(float v0, float v1, uint32_t& hw, uint32_t& lw){
    __half h0=__float2half_rn(v0), h1=__float2half_rn(v1);
    hw=(uint32_t)__half_as_ushort(h0)|((uint32_t)__half_as_ushort(h1)<<16);
    __half g0=__float2half_rn(v0-__half2float(h0)), g1=__float2half_rn(v1-__half2float(h1));
    lw=(uint32_t)__half_as_ushort(g0)|((uint32_t)__half_as_ushort(g1)<<16);
}

// ===================== merged prep (1 launch) =====================
__global__ void __launch_bounds__(128) prep_all(const float* __restrict__ st, const float* __restrict__ ac,
                                                const float* __restrict__ W1, const float* __restrict__ W2){
    const int b=blockIdx.x, tid=threadIdx.x;
    if(b<256){                                  // --- X: 128 rows -> two 64-row tiles ---
        int R=b*128+tid, t2=R>>6, rl=R&63;
        uint32_t wh[16], wl[16];
        #pragma unroll
        for(int i=0;i<16;i++){wh[i]=0;wl[i]=0;}
        #pragma unroll
        for(int kp=0;kp<12;kp++){
            int k=kp*2;
            float v0=0.f,v1=0.f;
            if(k<17)v0=st[R*17+k]; else if(k<23)v0=ac[R*6+k-17];
            if(k+1<17)v1=st[R*17+k+1]; else if(k+1<23)v1=ac[R*6+k+1-17];
            split2f(v0,v1,wh[kp],wl[kp]);
        }
        char* dh=(char*)&g_X[0][t2][0]; char* dl=(char*)&g_X[1][t2][0];
        #pragma unroll
        for(int u=0;u<4;u++){
            uint32_t off=sw64((uint32_t)(rl*64+u*16));
            *(uint4*)(dh+off)=make_uint4(wh[4*u],wh[4*u+1],wh[4*u+2],wh[4*u+3]);
            *(uint4*)(dl+off)=make_uint4(wl[4*u],wl[4*u+1],wl[4*u+2],wl[4*u+3]);
        }
    } else if(b<256+NQ){                        // --- W1 ---
        int n=b-256;
        for(int c=tid;c<256;c+=128){
            uint32_t w[16];
            #pragma unroll
            for(int i=0;i<16;i++) w[i]=0;
            #pragma unroll
            for(int kp=0;kp<12;kp++){
                int k=kp*2;
                float v0=(k<23)?W1[(n*23+k)*256+c]:0.f;
                float v1=(k+1<23)?W1[(n*23+k+1)*256+c]:0.f;
                w[kp]=h2(v0,v1);
            }
            char* d=(char*)&g_W1[n][0];
            #pragma unroll
            for(int u=0;u<4;u++){
                uint32_t off=sw64((uint32_t)(c*64+u*16));
                *(uint4*)(d+off)=make_uint4(w[4*u],w[4*u+1],w[4*u+2],w[4*u+3]);
            }
        }
    } else {                                    // --- W2 ---
        int e=b-256-NQ, n=e>>1, np=e&1, nl=tid;
        const float* src=W2+n*65536+np*128+nl;
        for(int kc=0;kc<4;kc++){
            uint32_t w[32];
            #pragma unroll
            for(int kp=0;kp<32;kp++){
                int k=kc*64+kp*2;
                w[kp]=h2(src[k*256],src[(k+1)*256]);
            }
            char* d=(char*)&g_W2[n][np][kc][0];
            #pragma unroll
            for(int u=0;u<8;u++){
                uint32_t off=sw128((uint32_t)(nl*128+u*16));
                *(uint4*)(d+off)=make_uint4(w[4*u],w[4*u+1],w[4*u+2],w[4*u+3]);
            }
        }
    }
}

// ===================== main: producer/consumer ping-pong =====================
// A2 2x32K @0, W2 128K @65536, W1 16K @196608, X 2x8K @212992, RED 1K @229376.
#define SM_A2  0
#define SM_W2  65536
#define SM_W1  196608
#define SM_X   212992
#define SM_RED 229376
#define SM_TOT 230400

__global__ void __launch_bounds__(512,1)
qmain(const float* __restrict__ b1,const float* __restrict__ b2,
      const float* __restrict__ W3,const float* __restrict__ b3,float* __restrict__ out){
    extern __shared__ char sm[];
    float* f=(float*)sm;
    const uint32_t sb=smem_u32(sm);
    const int tid=threadIdx.x, wid=tid>>5, lane=tid&31;
    const bool prod = wid<8;
    const int aRow=(lane&7)+((lane>>3)&1)*8, aCol=(lane>>4)*8;
    const int bRow=(lane&7)+((lane>>4)<<3),  bCol=((lane>>3)&1)*8;
    const int q=lane>>2, s2=(lane&3)*2;
    // producer layout: 2m x 4n
    const int pm=wid&1, pn=wid>>1, Rp=pm*32;
    // consumer layout: 2m x 4n over 256 cols
    const int cg=wid-8, cm=cg&1, cn=cg>>1, Rc=cm*32;
    const int np=cn>>1, nbase=(cn&1)*64;

    const int c=blockIdx.x;
    int u    = (c<88)? c*18 : 1584+(c-88)*17;
    const int uend = u + ((c<88)?18:17);

    while(u<uend){
        const int n=u>>9;
        const int seg_end = (uend < ((n+1)<<9)) ? uend : ((n+1)<<9);

        // ---- cold load: G0 = X(u)+W1, G1 = W2 ----
        {
            const char* xh=(const char*)&g_X[0][u&511][0];
            const char* xl=(const char*)&g_X[1][u&511][0];
            uint32_t xb=sb+SM_X+(uint32_t)((u&1)*8192);
            if(tid<256){ cpa16(xb+tid*16,xh+tid*16); cpa16(xb+4096+tid*16,xl+tid*16); }
            const char* w1=(const char*)&g_W1[n][0];
            for(int i=tid;i<1024;i+=512) cpa16(sb+SM_W1+i*16,w1+i*16);
            CP_COMMIT();
            const char* w2=(const char*)&g_W2[n][0][0][0];
            for(int i=tid;i<8192;i+=512) cpa16(sb+SM_W2+i*16,w2+i*16);
            CP_COMMIT();
        }
        CP_WAIT(1);
        __syncthreads();       // X(u) + W1 ready

        // ---- prologue: producer builds A2[u&1]; consumer waits W2 ----
        if(prod){
            if(u+1<seg_end){
                const char* xh=(const char*)&g_X[0][(u+1)&511][0];
                const char* xl=(const char*)&g_X[1][(u+1)&511][0];
                uint32_t xb=sb+SM_X+(uint32_t)(((u+1)&1)*8192);
                cpa16(xb+tid*16,xh+tid*16); cpa16(xb+4096+tid*16,xl+tid*16);
                CP_COMMIT();
            }
            // layer1(u) + epi1 -> A2[u&1]
            const uint32_t xb=sb+SM_X+(uint32_t)((u&1)*8192);
            float a1[2][8][4];
            #pragma unroll
            for(int mt=0;mt<2;mt++)
                #pragma unroll
                for(int nt=0;nt<8;nt++)
                    #pragma unroll
                    for(int e=0;e<4;e++) a1[mt][nt][e]=0.f;
            #pragma unroll
            for(int ks=0;ks<2;ks++){
                const int k=ks*16;
                uint32_t ah[2][4],al[2][4];
                #pragma unroll
                for(int mt=0;mt<2;mt++){
                    uint32_t o=sw64((uint32_t)((Rp+mt*16+aRow)*64+(k+aCol)*2));
                    ldm4(ah[mt],xb+o); ldm4(al[mt],xb+4096+o);
                }
                #pragma unroll
                for(int p=0;p<4;p++){
                    uint32_t ob=sw64((uint32_t)((pn*64+p*16+bRow)*64+(k+bCol)*2));
                    uint32_t bw[4]; ldm4(bw,sb+SM_W1+ob);
                    #pragma unroll
                    for(int mt=0;mt<2;mt++)
                        #pragma unroll
                        for(int sub=0;sub<2;sub++){
                            int nt=p*2+sub;
                            hmma(a1[mt][nt],ah[mt],bw[sub*2],bw[sub*2+1]);
                            hmma(a1[mt][nt],al[mt],bw[sub*2],bw[sub*2+1]);
                        }
                }
            }
            const float2* b1v=(const float2*)(b1+n*256);
            const uint32_t a2b=sb+SM_A2+(uint32_t)((u&1)*32768)+(uint32_t)(pn*8192);
            #pragma unroll
            for(int mt=0;mt<2;mt++){
                const int r0=Rp+mt*16+q;
                #pragma unroll
                for(int nt=0;nt<8;nt++){
                    const int c0=pn*64+nt*8+s2, kk=c0&63;
                    const float2 bb=__ldg(&b1v[c0>>1]);
                    *(uint32_t*)(sm+(a2b-sb)+sw128((uint32_t)(r0*128+kk*2)))
                        =h2(fmaxf(a1[mt][nt][0]+bb.x,0.f),fmaxf(a1[mt][nt][1]+bb.y,0.f));
                    *(uint32_t*)(sm+(a2b-sb)+sw128((uint32_t)((r0+8)*128+kk*2)))
                        =h2(fmaxf(a1[mt][nt][2]+bb.x,0.f),fmaxf(a1[mt][nt][3]+bb.y,0.f));
                }
            }
        } else {
            CP_WAIT(0);        // W2 resident
        }
        __syncthreads();       // A2[u&1] ready, W2 ready

        // ---- steady pipeline ----
        for(; u<seg_end; u++){
            if(prod){
                if(u+1<seg_end){
                    CP_WAIT(0);   // X(u+1) landed
                    const int u1=u+1;
                    const uint32_t xb=sb+SM_X+(uint32_t)((u1&1)*8192);
                    float a1[2][8][4];
                    #pragma unroll
                    for(int mt=0;mt<2;mt++)
                        #pragma unroll
                        for(int nt=0;nt<8;nt++)
                            #pragma unroll
                            for(int e=0;e<4;e++) a1[mt][nt][e]=0.f;
                    #pragma unroll
                    for(int ks=0;ks<2;ks++){
                        const int k=ks*16;
                        uint32_t ah[2][4],al[2][4];
                        #pragma unroll
                        for(int mt=0;mt<2;mt++){
                            uint32_t o=sw64((uint32_t)((Rp+mt*16+aRow)*64+(k+aCol)*2));
                            ldm4(ah[mt],xb+o); ldm4(al[mt],xb+4096+o);
                        }
                        #pragma unroll
                        for(int p=0;p<4;p++){
                            uint32_t ob=sw64((uint32_t)((pn*64+p*16+bRow)*64+(k+bCol)*2));
                            uint32_t bw[4]; ldm4(bw,sb+SM_W1+ob);
                            #pragma unroll
                            for(int mt=0;mt<2;mt++)
                                #pragma unroll
                                for(int sub=0;sub<2;sub++){
                                    int nt=p*2+sub;
                                    hmma(a1[mt][nt],ah[mt],bw[sub*2],bw[sub*2+1]);
                                    hmma(a1[mt][nt],al[mt],bw[sub*2],bw[sub*2+1]);
                                }
                        }
                    }
                    if(u+2<seg_end){
                        const char* xh=(const char*)&g_X[0][(u+2)&511][0];
                        const char* xl=(const char*)&g_X[1][(u+2)&511][0];
                        uint32_t xb2=sb+SM_X+(uint32_t)((u&1)*8192);
                        cpa16(xb2+tid*16,xh+tid*16); cpa16(xb2+4096+tid*16,xl+tid*16);
                        CP_COMMIT();
                    }
                    const float2* b1v=(const float2*)(b1+n*256);
                    const uint32_t a2b=sb+SM_A2+(uint32_t)((u1&1)*32768)+(uint32_t)(pn*8192);
                    #pragma unroll
                    for(int mt=0;mt<2;mt++){
                        const int r0=Rp+mt*16+q;
                        #pragma unroll
                        for(int nt=0;nt<8;nt++){
                            const int c0=pn*64+nt*8+s2, kk=c0&63;
                            const float2 bb=__ldg(&b1v[c0>>1]);
                            *(uint32_t*)(sm+(a2b-sb)+sw128((uint32_t)(r0*128+kk*2)))
                                =h2(fmaxf(a1[mt][nt][0]+bb.x,0.f),fmaxf(a1[mt][nt][1]+bb.y,0.f));
                            *(uint32_t*)(sm+(a2b-sb)+sw128((uint32_t)((r0+8)*128+kk*2)))
                                =h2(fmaxf(a1[mt][nt][2]+bb.x,0.f),fmaxf(a1[mt][nt][3]+bb.y,0.f));
                        }
                    }
                }
            } else {
                // ---- consumer: layer2(u) + fold + output ----
                float acc[2][8][4];
                #pragma unroll
                for(int mt=0;mt<2;mt++)
                    #pragma unroll
                    for(int nt=0;nt<8;nt++)
                        #pragma unroll
                        for(int e=0;e<4;e++) acc[mt][nt][e]=0.f;
                const uint32_t a2base=sb+SM_A2+(uint32_t)((u&1)*32768);
                #pragma unroll 1
                for(int kc=0;kc<4;kc++){
                    const uint32_t ab=a2base+(uint32_t)(kc*8192);
                    const uint32_t bbase=sb+SM_W2+(uint32_t)((np*4+kc)*16384);
                    #pragma unroll
                    for(int ks=0;ks<4;ks++){
                        const int k=ks*16;
                        uint32_t ah[2][4];
                        #pragma unroll
                        for(int mt=0;mt<2;mt++){
                            uint32_t o=sw128((uint32_t)((Rc+mt*16+aRow)*128+(k+aCol)*2));
                            ldm4(ah[mt],ab+o);
                        }
                        #pragma unroll
                        for(int p4=0;p4<4;p4++){
                            uint32_t ob=sw128((uint32_t)((nbase+p4*16+bRow)*128+(k+bCol)*2));
                            uint32_t bf[4]; ldm4(bf,bbase+ob);
                            #pragma unroll
                            for(int mt=0;mt<2;mt++)
                                #pragma unroll
                                for(int sub=0;sub<2;sub++){
                                    int nt=p4*2+sub;
                                    hmma(acc[mt][nt],ah[mt],bf[sub*2],bf[sub*2+1]);
                                }
                        }
                    }
                }
                float rowsum[4]={0.f,0.f,0.f,0.f};
                const float2* b2v=(const float2*)(b2+n*256);
                const float2* w3v=(const float2*)(W3+n*256);
                #pragma unroll
                for(int mt=0;mt<2;mt++)
                    #pragma unroll
                    for(int nt=0;nt<8;nt++){
                        const int c0=np*128+nbase+nt*8+s2;
                        const float2 bb=__ldg(&b2v[c0>>1]);
                        const float2 uu=__ldg(&w3v[c0>>1]);
                        rowsum[mt*2+0]+=fmaxf(acc[mt][nt][0]+bb.x,0.f)*uu.x
                                      +fmaxf(acc[mt][nt][1]+bb.y,0.f)*uu.y;
                        rowsum[mt*2+1]+=fmaxf(acc[mt][nt][2]+bb.x,0.f)*uu.x
                                      +fmaxf(acc[mt][nt][3]+bb.y,0.f)*uu.y;
                    }
                #pragma unroll
                for(int i=0;i<4;i++){
                    float v=rowsum[i];
                    v+=__shfl_xor_sync(0xffffffffu,v,1);
                    v+=__shfl_xor_sync(0xffffffffu,v,2);
                    if((lane&3)==0) f[SM_RED/4+cn*64+Rc+(i>>1)*16+(i&1)*8+q]=v;
                }
                asm volatile("bar.sync 1, 256;":::"memory");
                const int ctid=tid-256;
                if(ctid<64){
                    const float* red=f+SM_RED/4;
                    out[n*BSZ+(u&511)*64+ctid]=red[ctid]+red[64+ctid]+red[128+ctid]+red[192+ctid]+__ldg(b3+n);
                }
            }
            __syncthreads();
        }
    }
}

extern "C" void kernel_launch(void* const* d_in, const int* in_sizes, int n_in,
                              void* d_out, int out_size){
    const float* state =(const float*)d_in[0];
    const float* action=(const float*)d_in[1];
    const float* W1=(const float*)d_in[2];
    const float* b1=(const float*)d_in[3];
    const float* W2=(const float*)d_in[4];
    const float* b2=(const float*)d_in[5];
    const float* W3=(const float*)d_in[6];
    const float* b3=(const float*)d_in[7];
    float* out=(float*)d_out;

    prep_all<<<256+NQ+NQ*2,128>>>(state,action,W1,W2);

    cudaFuncSetAttribute(qmain,cudaFuncAttributeMaxDynamicSharedMemorySize,SM_TOT);
    qmain<<<GRID,512,SM_TOT>>>(b1,b2,W3,b3,out);
}